// round 7
// baseline (speedup 1.0000x reference)
#include <cuda_runtime.h>
#include <cuda_bf16.h>

// LinearPositionInterpolation:
//   index: (n,) int32 sorted keypoints (n=129, spacing 32 -> m=4096)
//   value: (batch, n, dim) float32   (batch=32, dim=256)
//   out:   (batch, m, dim) float32, rows p=1..m (excludes start point)
//
// R7 = R6 (max-occupancy, evict-first .cs float4 stores) with 2x finer
// blocks to halve ramp-down tail loss: 4 blocks per (b,seg) tile,
// 128 threads each (2 row-lanes x 64 float4 dim-lanes), global row
// stride 8. 16384 blocks, 16 resident/SM -> shorter blocks, smoother tail.

static constexpr int DIM    = 256;       // per metadata
static constexpr int DIM4   = DIM / 4;   // 64 float4 lanes per row
static constexpr int SPLIT  = 4;         // blocks per tile
static constexpr int TPB    = 128;       // 2 row lanes x 64 dim lanes

static constexpr int RLANES_BLK  = TPB / DIM4;         // 2
static constexpr int RLANES_TILE = SPLIT * RLANES_BLK; // 8

__global__ __launch_bounds__(TPB, 16)
void lpi_kernel(const int* __restrict__ index,
                const float4* __restrict__ value,
                float4* __restrict__ out,
                int n, int m)
{
    const int nseg = n - 1;
    const int tile = blockIdx.x >> 2;            // (b,seg) tile
    const int part = blockIdx.x & (SPLIT - 1);   // which row subset
    const int seg  = tile % nseg;
    const int b    = tile / nseg;
    const int d    = threadIdx.x & (DIM4 - 1);   // dim lane 0..63
    const int rl   = (threadIdx.x >> 6) + part * RLANES_BLK; // row lane 0..7

    const int base = index[0];
    const int x0   = index[seg]     - base;      // L2-hot
    const int x1   = index[seg + 1] - base;
    const int len  = x1 - x0;                    // rows in this segment
    const float inv = 1.0f / (float)len;

    const float4* v = value + (b * n + seg) * DIM4 + d;
    const float4 y0 = __ldg(v);
    const float4 y1 = __ldg(v + DIM4);
    const float4 dy = make_float4(y1.x - y0.x, y1.y - y0.y,
                                  y1.z - y0.z, y1.w - y0.w);

    // output row for p = x0 + pc is (x0 + pc - 1) (0-based, p starts at 1)
    float4* o = out + (b * m + x0 + rl) * DIM4 + d;
    const int ostep = RLANES_TILE * DIM4;

    #pragma unroll 4
    for (int pc = 1 + rl; pc <= len; pc += RLANES_TILE) {
        const float w = (float)pc * inv;
        float4 r;
        r.x = fmaf(dy.x, w, y0.x);
        r.y = fmaf(dy.y, w, y0.y);
        r.z = fmaf(dy.z, w, y0.z);
        r.w = fmaf(dy.w, w, y0.w);
        __stcs(o, r);                            // evict-first streaming store
        o += ostep;
    }
}

extern "C" void kernel_launch(void* const* d_in, const int* in_sizes, int n_in,
                              void* d_out, int out_size)
{
    const int*    index = (const int*)d_in[0];
    const float4* value = (const float4*)d_in[1];
    float4*       out   = (float4*)d_out;

    const int n     = in_sizes[0];                 // 129
    const int batch = in_sizes[1] / (n * DIM);     // 32
    const int m     = out_size / (batch * DIM);    // 4096

    const int nseg = n - 1;
    dim3 grid(batch * nseg * SPLIT);               // 16384 blocks
    dim3 block(TPB);                               // 128 threads
    lpi_kernel<<<grid, block>>>(index, value, out, n, m);
}

// round 8
// speedup vs baseline: 1.3131x; 1.3131x over previous
#include <cuda_runtime.h>
#include <cuda_bf16.h>

// LinearPositionInterpolation:
//   index: (n,) int32 sorted keypoints (n=129, spacing 32 -> m=4096)
//   value: (batch, n, dim) float32   (batch=32, dim=256)
//   out:   (batch, m, dim) float32, rows p=1..m (excludes start point)
//
// R8 = R6 geometry EXACTLY (8192 blocks x 128 threads, 2 blocks per
// (b,seg) tile, 2 row-lanes/block, 16 blocks/SM) with ONE change:
// write-through (st.global.wt) stores instead of evict-first (.cs).
// A/B test of the steady-state L2 dirty-eviction-debt model: .wt creates
// no dirty lines, so back-to-back graph replays don't stall on evicting
// the previous replay's 134 MB of dirt.

static constexpr int DIM    = 256;       // per metadata
static constexpr int DIM4   = DIM / 4;   // 64 float4 lanes per row
static constexpr int HALF   = 2;         // blocks per tile
static constexpr int TPB    = 128;       // 2 row lanes x 64 dim lanes

static constexpr int RLANES_BLK  = TPB / DIM4;        // 2
static constexpr int RLANES_TILE = HALF * RLANES_BLK; // 4

__device__ __forceinline__ void stg_wt_v4(float4* p, const float4& r) {
    asm volatile("st.global.wt.v4.f32 [%0], {%1,%2,%3,%4};"
                 :: "l"(p), "f"(r.x), "f"(r.y), "f"(r.z), "f"(r.w)
                 : "memory");
}

__global__ __launch_bounds__(TPB, 16)
void lpi_kernel(const int* __restrict__ index,
                const float4* __restrict__ value,
                float4* __restrict__ out,
                int n, int m)
{
    const int nseg = n - 1;
    const int tile = blockIdx.x >> 1;            // (b,seg) tile
    const int half = blockIdx.x & 1;             // which half of row set
    const int seg  = tile % nseg;
    const int b    = tile / nseg;
    const int d    = threadIdx.x & (DIM4 - 1);   // dim lane 0..63
    const int rl   = (threadIdx.x >> 6) + half * RLANES_BLK; // row lane 0..3

    const int base = index[0];
    const int x0   = index[seg]     - base;      // L2-hot
    const int x1   = index[seg + 1] - base;
    const int len  = x1 - x0;                    // rows in this segment
    const float inv = 1.0f / (float)len;

    const float4* v = value + (b * n + seg) * DIM4 + d;
    const float4 y0 = __ldg(v);
    const float4 y1 = __ldg(v + DIM4);
    const float4 dy = make_float4(y1.x - y0.x, y1.y - y0.y,
                                  y1.z - y0.z, y1.w - y0.w);

    // output row for p = x0 + pc is (x0 + pc - 1) (0-based, p starts at 1)
    float4* o = out + (b * m + x0 + rl) * DIM4 + d;
    const int ostep = RLANES_TILE * DIM4;

    #pragma unroll 8
    for (int pc = 1 + rl; pc <= len; pc += RLANES_TILE) {
        const float w = (float)pc * inv;
        float4 r;
        r.x = fmaf(dy.x, w, y0.x);
        r.y = fmaf(dy.y, w, y0.y);
        r.z = fmaf(dy.z, w, y0.z);
        r.w = fmaf(dy.w, w, y0.w);
        stg_wt_v4(o, r);                         // write-through store
        o += ostep;
    }
}

extern "C" void kernel_launch(void* const* d_in, const int* in_sizes, int n_in,
                              void* d_out, int out_size)
{
    const int*    index = (const int*)d_in[0];
    const float4* value = (const float4*)d_in[1];
    float4*       out   = (float4*)d_out;

    const int n     = in_sizes[0];                 // 129
    const int batch = in_sizes[1] / (n * DIM);     // 32
    const int m     = out_size / (batch * DIM);    // 4096

    const int nseg = n - 1;
    dim3 grid(batch * nseg * HALF);                // 8192 blocks
    dim3 block(TPB);                               // 128 threads
    lpi_kernel<<<grid, block>>>(index, value, out, n, m);
}

// round 9
// speedup vs baseline: 1.4465x; 1.1015x over previous
#include <cuda_runtime.h>
#include <cuda_bf16.h>

// LinearPositionInterpolation:
//   index: (n,) int32 sorted keypoints (n=129, spacing 32 -> m=4096)
//   value: (batch, n, dim) float32   (batch=32, dim=256)
//   out:   (batch, m, dim) float32, rows p=1..m (excludes start point)
//
// R9 = R6 (best: 8192 blocks x 128 threads, 2 blocks/tile, .cs stores,
// 16 blocks/SM) + setup-cost cuts:
//   - nseg is pow2 at runtime -> host passes log2, seg/b via shift/mask
//   - fully unrolled fast path for the uniform case len == 32:
//     8 independent stores, addresses+weights front-computed (max MLP)
//   - generic loop fallback keeps correctness for arbitrary spacing.

static constexpr int DIM    = 256;       // per metadata
static constexpr int DIM4   = DIM / 4;   // 64 float4 lanes per row
static constexpr int HALF   = 2;         // blocks per tile
static constexpr int TPB    = 128;       // 2 row lanes x 64 dim lanes

static constexpr int RLANES_BLK  = TPB / DIM4;        // 2
static constexpr int RLANES_TILE = HALF * RLANES_BLK; // 4
static constexpr int FAST_LEN    = 8 * RLANES_TILE;   // 32 rows

__global__ __launch_bounds__(TPB, 16)
void lpi_kernel(const int* __restrict__ index,
                const float4* __restrict__ value,
                float4* __restrict__ out,
                int n, int m, int seg_shift)   // seg_shift = log2(nseg) or -1
{
    const int nseg = n - 1;
    const int tile = blockIdx.x >> 1;            // (b,seg) tile
    const int half = blockIdx.x & 1;             // which half of row set
    int seg, b;
    if (seg_shift >= 0) {                        // pow2 fast mapping
        seg = tile & (nseg - 1);
        b   = tile >> seg_shift;
    } else {
        seg = tile % nseg;
        b   = tile / nseg;
    }
    const int d  = threadIdx.x & (DIM4 - 1);     // dim lane 0..63
    const int rl = (threadIdx.x >> 6) + half * RLANES_BLK; // row lane 0..3

    const int base = index[0];
    const int x0   = index[seg]     - base;      // L2-hot
    const int x1   = index[seg + 1] - base;
    const int len  = x1 - x0;                    // rows in this segment
    const float inv = 1.0f / (float)len;

    const float4* v = value + (b * n + seg) * DIM4 + d;
    const float4 y0 = __ldg(v);
    const float4 y1 = __ldg(v + DIM4);
    const float4 dy = make_float4(y1.x - y0.x, y1.y - y0.y,
                                  y1.z - y0.z, y1.w - y0.w);

    // output row for p = x0 + pc is (x0 + pc - 1) (0-based, p starts at 1)
    float4* o = out + (b * m + x0 + rl) * DIM4 + d;
    const int ostep = RLANES_TILE * DIM4;

    if (len == FAST_LEN) {
        // uniform spacing: exactly 8 stores/thread, fully unrolled,
        // all independent -> front-batched STG.128
        #pragma unroll
        for (int i = 0; i < 8; i++) {
            const float w = (float)(1 + rl + i * RLANES_TILE) * inv;
            float4 r;
            r.x = fmaf(dy.x, w, y0.x);
            r.y = fmaf(dy.y, w, y0.y);
            r.z = fmaf(dy.z, w, y0.z);
            r.w = fmaf(dy.w, w, y0.w);
            __stcs(o + i * ostep, r);
        }
    } else {
        #pragma unroll 4
        for (int pc = 1 + rl; pc <= len; pc += RLANES_TILE) {
            const float w = (float)pc * inv;
            float4 r;
            r.x = fmaf(dy.x, w, y0.x);
            r.y = fmaf(dy.y, w, y0.y);
            r.z = fmaf(dy.z, w, y0.z);
            r.w = fmaf(dy.w, w, y0.w);
            __stcs(o, r);
            o += ostep;
        }
    }
}

extern "C" void kernel_launch(void* const* d_in, const int* in_sizes, int n_in,
                              void* d_out, int out_size)
{
    const int*    index = (const int*)d_in[0];
    const float4* value = (const float4*)d_in[1];
    float4*       out   = (float4*)d_out;

    const int n     = in_sizes[0];                 // 129
    const int batch = in_sizes[1] / (n * DIM);     // 32
    const int m     = out_size / (batch * DIM);    // 4096

    const int nseg = n - 1;                        // 128 (pow2)
    int seg_shift = -1;
    if ((nseg & (nseg - 1)) == 0) {
        seg_shift = 0;
        while ((1 << seg_shift) < nseg) seg_shift++;
    }

    dim3 grid(batch * nseg * HALF);                // 8192 blocks
    dim3 block(TPB);                               // 128 threads
    lpi_kernel<<<grid, block>>>(index, value, out, n, m, seg_shift);
}